// round 14
// baseline (speedup 1.0000x reference)
#include <cuda_runtime.h>
#include <cuda_fp16.h>
#include <cstdint>
#include <cstddef>

// CompetitiveNetwork via mma.sync.
// R13: cheap phase fully fp16. Error is truncation-dominated (rel_err
// invariant across bf16/fp16 operands => arithmetic noise <<), so the cheap
// phase uses f16-accumulate MMA (m16n8k16.f16.f16.f16.f16). Its D fragment
// is ALREADY in A-fragment packing -> zero repack: D regs of one step are
// the A regs of the next (ping-pong arrays). Nonlinearity in half2
// (h2rcp / hmul2). +1 folded as C = (1,1). Precise phase (2 pairs + final
// BF, fp32 accum, 3-term fp16 split) and epilogue unchanged from R12.

#define THREADS 256
#define ROWS_PER_CTA 128
#define N_DIM 64
#define CHEAP_ITERS 15

typedef unsigned int u32;

#define MATS_BYTES (6 * 8192)              // fragment-ordered split matrices
#define AT_OFF     MATS_BYTES
#define AT_STRIDE  66
#define SMEM_TOTAL (AT_OFF + 128 * AT_STRIDE * 4)   // 82944

#define H2_ONE 0x3C003C00u

__device__ __forceinline__ float rcpa(float x) {
    float r; asm("rcp.approx.f32 %0, %1;" : "=f"(r) : "f"(x)); return r;
}
__device__ __forceinline__ u32 packh2(float x0, float x1) {
    __half2 h = __floats2half2_rn(x0, x1);
    return *reinterpret_cast<u32*>(&h);
}
__device__ __forceinline__ void split2h(float x0, float x1, u32 &hi, u32 &lo) {
    __half2 h = __floats2half2_rn(x0, x1);
    hi = *reinterpret_cast<u32*>(&h);
    float h0 = __low2float(h), h1 = __high2float(h);
    __half2 l = __floats2half2_rn(x0 - h0, x1 - h1);
    lo = *reinterpret_cast<u32*>(&l);
}
__device__ __forceinline__ u32 h2rcp_u(u32 x) {
    __half2 v = h2rcp(*reinterpret_cast<__half2*>(&x));
    return *reinterpret_cast<u32*>(&v);
}
__device__ __forceinline__ u32 hmul2_u(u32 a, u32 b) {
    __half2 r = __hmul2(*reinterpret_cast<__half2*>(&a),
                        *reinterpret_cast<__half2*>(&b));
    return *reinterpret_cast<u32*>(&r);
}

// fragment-order store: element at logical (k, n) of a B operand
__device__ __forceinline__ void st_frag(__half* base, int k, int n, __half v) {
    int lane = ((n & 7) << 2) | ((k & 7) >> 1);
    int w2   = (((k >> 4) & 1) << 1) | ((k >> 3) & 1);
    int idx  = ((k >> 5) << 11) | ((n >> 3) << 8) | (lane << 3)
             | (w2 << 1) | (k & 1);
    base[idx] = v;
}

// ---- fp32-accumulate MMAs (precise phase / epilogue) ----------------------
#define MMA(d, a, b0, b1)                                                      \
    asm("mma.sync.aligned.m16n8k16.row.col.f32.f16.f16.f32 "                   \
        "{%0,%1,%2,%3}, {%4,%5,%6,%7}, {%8,%9}, {%0,%1,%2,%3};"                \
        : "+f"((d)[0]), "+f"((d)[1]), "+f"((d)[2]), "+f"((d)[3])               \
        : "r"((a)[0]), "r"((a)[1]), "r"((a)[2]), "r"((a)[3]),                  \
          "r"(b0), "r"(b1))

#define MMA_Z(d, a, b0, b1)                                                    \
    asm("mma.sync.aligned.m16n8k16.row.col.f32.f16.f16.f32 "                   \
        "{%0,%1,%2,%3}, {%4,%5,%6,%7}, {%8,%9}, {%10,%10,%10,%10};"            \
        : "=f"((d)[0]), "=f"((d)[1]), "=f"((d)[2]), "=f"((d)[3])               \
        : "r"((a)[0]), "r"((a)[1]), "r"((a)[2]), "r"((a)[3]),                  \
          "r"(b0), "r"(b1), "f"(0.0f))

#define MMA_ONE(d, a, b0, b1)                                                  \
    asm("mma.sync.aligned.m16n8k16.row.col.f32.f16.f16.f32 "                   \
        "{%0,%1,%2,%3}, {%4,%5,%6,%7}, {%8,%9}, {%10,%10,%10,%10};"            \
        : "=f"((d)[0]), "=f"((d)[1]), "=f"((d)[2]), "=f"((d)[3])               \
        : "r"((a)[0]), "r"((a)[1]), "r"((a)[2]), "r"((a)[3]),                  \
          "r"(b0), "r"(b1), "f"(1.0f))

// ---- f16-accumulate MMAs (cheap phase) -------------------------------------
// first MMA: C = (1,1) packed  ->  d = A*B + 1
#define MMAH_ONE(d0, d1, a0, a1, a2, a3, b0, b1)                               \
    asm("mma.sync.aligned.m16n8k16.row.col.f16.f16.f16.f16 "                   \
        "{%0,%1}, {%2,%3,%4,%5}, {%6,%7}, {%8,%8};"                            \
        : "=r"(d0), "=r"(d1)                                                   \
        : "r"(a0), "r"(a1), "r"(a2), "r"(a3),                                  \
          "r"(b0), "r"(b1), "r"(H2_ONE))

#define MMAH(d0, d1, a0, a1, a2, a3, b0, b1)                                   \
    asm("mma.sync.aligned.m16n8k16.row.col.f16.f16.f16.f16 "                   \
        "{%0,%1}, {%2,%3,%4,%5}, {%6,%7}, {%0,%1};"                            \
        : "+r"(d0), "+r"(d1)                                                   \
        : "r"(a0), "r"(a1), "r"(a2), "r"(a3),                                  \
          "r"(b0), "r"(b1))

__global__ void __launch_bounds__(THREADS, 1)
cnet_mma_kernel(const float* __restrict__ AT,
                const float* __restrict__ Kraw,
                const float* __restrict__ BTraw,
                const float* __restrict__ Wraw,
                const float* __restrict__ braw,
                float* __restrict__ out)
{
    extern __shared__ char smc[];
    __half* mats = reinterpret_cast<__half*>(smc);
    float* ats = reinterpret_cast<float*>(smc + AT_OFF);   // [128][66] f32

    const int tid  = threadIdx.x;
    const int w    = tid >> 5;          // warp 0..7 -> rows [16w, 16w+16)
    const int lane = tid & 31;
    const int g    = lane >> 2;
    const int t    = lane & 3;
    const int rb   = w * 16;
    const int bid  = blockIdx.x;

    // ---- setup: exp/clip K, bt-folded fragment-ordered split matrices ------
    // mats 0/1: KT hi/lo   B(k=i,n=j) = K[i][j]           (BF-step)
    // mats 2/3: K'  hi/lo  B(k=j,n=i) = K[i][j]*bt[j]     (AF-step)
    // mats 4/5: M'  hi/lo  B(k=i,n=j) = K[i][j]*W*bt[j]   (epilogue)
    for (int idx = tid; idx < 4096; idx += THREADS) {
        int i = idx >> 6, j = idx & 63;
        float k = fminf(__expf(Kraw[idx]), 1000.0f);
        float btj = fminf(__expf(BTraw[j]), 1000.0f);
        float wv = fminf(fmaxf(Wraw[idx], -10.0f), 10.0f);
        float kp = k * btj;
        float m  = k * wv * btj;
        __half kh = __float2half_rn(k);
        __half kl = __float2half_rn(k - __half2float(kh));
        __half ph = __float2half_rn(kp);
        __half pl = __float2half_rn(kp - __half2float(ph));
        __half mh = __float2half_rn(m);
        __half ml = __float2half_rn(m - __half2float(mh));
        st_frag(mats + 0 * 4096, i, j, kh);
        st_frag(mats + 1 * 4096, i, j, kl);
        st_frag(mats + 2 * 4096, j, i, ph);
        st_frag(mats + 3 * 4096, j, i, pl);
        st_frag(mats + 4 * 4096, i, j, mh);
        st_frag(mats + 5 * 4096, i, j, ml);
    }
    {
        const float4* atg = reinterpret_cast<const float4*>(
            AT + (size_t)bid * (ROWS_PER_CTA * N_DIM));
        for (int idx = tid; idx < 2048; idx += THREADS) {
            float4 v = atg[idx];
            int r = idx >> 4, c = (idx & 15) << 2;
            float* p = ats + r * AT_STRIDE + c;
            p[0] = v.x; p[1] = v.y; p[2] = v.z; p[3] = v.w;
        }
    }
    __syncthreads();

    const int rlo = (rb + g) * AT_STRIDE;
    const int rhi = (rb + 8 + g) * AT_STRIDE;

    // ---- AT cached in half2 for the cheap AF nonlinearity -------------------
    // atc2[nt][0] = (AT[g, 8nt+2t], AT[g, 8nt+2t+1]); [1] = row g+8
    u32 atc2[8][2];
    #pragma unroll
    for (int nt = 0; nt < 8; nt++) {
        int cb = 8 * nt + 2 * t;
        float2 plo = *reinterpret_cast<const float2*>(ats + rlo + cb);
        float2 phi = *reinterpret_cast<const float2*>(ats + rhi + cb);
        atc2[nt][0] = packh2(plo.x, plo.y);
        atc2[nt][1] = packh2(phi.x, phi.y);
    }

    // ---- cheap-phase state: ping-pong f16 frags (D layout == A layout) -----
    // S[nt][0] = (row g, cols 8nt+2t pair), S[nt][1] = (row g+8, ...)
    u32 S[8][2], D[8][2];
    #pragma unroll
    for (int nt = 0; nt < 8; nt++) {          // initial AF = fp16(AT)
        S[nt][0] = atc2[nt][0];
        S[nt][1] = atc2[nt][1];
    }

    const uint4* __restrict__ frag = reinterpret_cast<const uint4*>(smc) + lane;

    // cheap matvec: DST = SRC-state @ B + 1 (f16 accumulate)
    // a-frag for kt = {SRC[2kt][0], SRC[2kt][1], SRC[2kt+1][0], SRC[2kt+1][1]}
#define STEP_CHEAP_H(MH, SRC, DST)                                             \
    do {                                                                       \
        _Pragma("unroll")                                                      \
        for (int nt = 0; nt < 8; nt++) {                                       \
            uint4 h0 = frag[(MH) * 512 +       nt * 32];                       \
            uint4 h1 = frag[(MH) * 512 + 256 + nt * 32];                       \
            MMAH_ONE(DST[nt][0], DST[nt][1],                                   \
                     SRC[0][0], SRC[0][1], SRC[1][0], SRC[1][1], h0.x, h0.y);  \
            MMAH(DST[nt][0], DST[nt][1],                                       \
                 SRC[2][0], SRC[2][1], SRC[3][0], SRC[3][1], h0.z, h0.w);      \
            MMAH(DST[nt][0], DST[nt][1],                                       \
                 SRC[4][0], SRC[4][1], SRC[5][0], SRC[5][1], h1.x, h1.y);      \
            MMAH(DST[nt][0], DST[nt][1],                                       \
                 SRC[6][0], SRC[6][1], SRC[7][0], SRC[7][1], h1.z, h1.w);      \
        }                                                                      \
    } while (0)

    // ---- phase 1: 15 cheap iterations, pure fp16, zero repack ---------------
    #pragma unroll 1
    for (int it = 0; it < CHEAP_ITERS; ++it) {
        STEP_CHEAP_H(0, S, D);                // BF-step: D = KT^T(S) + 1
        #pragma unroll
        for (int nt = 0; nt < 8; nt++) {      // BF' = rcp(D)
            D[nt][0] = h2rcp_u(D[nt][0]);
            D[nt][1] = h2rcp_u(D[nt][1]);
        }
        STEP_CHEAP_H(2, D, S);                // AF-step: S = K'(D) + 1
        #pragma unroll
        for (int nt = 0; nt < 8; nt++) {      // AF = AT * rcp(S)
            S[nt][0] = hmul2_u(atc2[nt][0], h2rcp_u(S[nt][0]));
            S[nt][1] = hmul2_u(atc2[nt][1], h2rcp_u(S[nt][1]));
        }
    }

    // ---- precision boundary: AF (f16) -> split A frags ----------------------
    u32 ah[4][4], al[4][4];
    #pragma unroll
    for (int kt = 0; kt < 4; kt++) {
        ah[kt][0] = S[2*kt][0];
        ah[kt][1] = S[2*kt][1];
        ah[kt][2] = S[2*kt+1][0];
        ah[kt][3] = S[2*kt+1][1];
        #pragma unroll
        for (int r = 0; r < 4; r++) al[kt][r] = 0u;
    }

    float d[8][4];

    // full matvec: d = (Ah+Al) @ Bh + Ah @ Bl + BIAS
#define MMA_PHASE_FULL(MH, FIRST)                                              \
    do {                                                                       \
        _Pragma("unroll")                                                      \
        for (int nt = 0; nt < 8; nt++) {                                       \
            uint4 h0 = frag[(MH) * 512 +       nt * 32];                       \
            uint4 h1 = frag[(MH) * 512 + 256 + nt * 32];                       \
            uint4 l0 = frag[((MH)+1) * 512 +       nt * 32];                   \
            uint4 l1 = frag[((MH)+1) * 512 + 256 + nt * 32];                   \
            FIRST(d[nt], ah[0], h0.x, h0.y);                                   \
            MMA(d[nt], al[0], h0.x, h0.y);                                     \
            MMA(d[nt], ah[0], l0.x, l0.y);                                     \
            MMA(d[nt], ah[1], h0.z, h0.w);                                     \
            MMA(d[nt], al[1], h0.z, h0.w);                                     \
            MMA(d[nt], ah[1], l0.z, l0.w);                                     \
            MMA(d[nt], ah[2], h1.x, h1.y);                                     \
            MMA(d[nt], al[2], h1.x, h1.y);                                     \
            MMA(d[nt], ah[2], l1.x, l1.y);                                     \
            MMA(d[nt], ah[3], h1.z, h1.w);                                     \
            MMA(d[nt], al[3], h1.z, h1.w);                                     \
            MMA(d[nt], ah[3], l1.z, l1.w);                                     \
        }                                                                      \
    } while (0)

#define BF_NONLIN()                                                            \
    do {                                                                       \
        _Pragma("unroll")                                                      \
        for (int nt = 0; nt < 8; nt++) {                                       \
            d[nt][0] = rcpa(d[nt][0]);                                         \
            d[nt][1] = rcpa(d[nt][1]);                                         \
            d[nt][2] = rcpa(d[nt][2]);                                         \
            d[nt][3] = rcpa(d[nt][3]);                                         \
        }                                                                      \
    } while (0)

#define AF_NONLIN()                                                            \
    do {                                                                       \
        _Pragma("unroll")                                                      \
        for (int nt = 0; nt < 8; nt++) {                                       \
            int cb = 8 * nt + 2 * t;                                           \
            float2 plo = *reinterpret_cast<const float2*>(ats + rlo + cb);     \
            float2 phi = *reinterpret_cast<const float2*>(ats + rhi + cb);     \
            d[nt][0] = plo.x * rcpa(d[nt][0]);                                 \
            d[nt][1] = plo.y * rcpa(d[nt][1]);                                 \
            d[nt][2] = phi.x * rcpa(d[nt][2]);                                 \
            d[nt][3] = phi.y * rcpa(d[nt][3]);                                 \
        }                                                                      \
    } while (0)

#define REPACK_FULL()                                                          \
    do {                                                                       \
        _Pragma("unroll")                                                      \
        for (int kt = 0; kt < 4; kt++) {                                       \
            split2h(d[2*kt][0],   d[2*kt][1],   ah[kt][0], al[kt][0]);         \
            split2h(d[2*kt][2],   d[2*kt][3],   ah[kt][1], al[kt][1]);         \
            split2h(d[2*kt+1][0], d[2*kt+1][1], ah[kt][2], al[kt][2]);         \
            split2h(d[2*kt+1][2], d[2*kt+1][3], ah[kt][3], al[kt][3]);         \
        }                                                                      \
    } while (0)

    // ---- phase 2: 2 precise BF/AF pairs, then final BF ----------------------
    #pragma unroll 1
    for (int it = 0; it < 2; ++it) {
        MMA_PHASE_FULL(0, MMA_ONE);
        BF_NONLIN();
        REPACK_FULL();
        MMA_PHASE_FULL(2, MMA_ONE);
        AF_NONLIN();
        REPACK_FULL();
    }

    // final BF step: keep fp32 BF' for the output contraction
    MMA_PHASE_FULL(0, MMA_ONE);
    BF_NONLIN();

    // stash final BF' (fp32) into the AT region (AT dead; same-lane rw)
    #pragma unroll
    for (int nt = 0; nt < 8; nt++) {
        int cb = 8 * nt + 2 * t;
        *reinterpret_cast<float2*>(ats + rlo + cb) =
            make_float2(d[nt][0], d[nt][1]);
        *reinterpret_cast<float2*>(ats + rhi + cb) =
            make_float2(d[nt][2], d[nt][3]);
    }

    // epilogue: H = AF @ M' (C = 0); y = sum_j BF'_j H_j
    MMA_PHASE_FULL(4, MMA_Z);

    float y0 = 0.f, y1 = 0.f;
    #pragma unroll
    for (int nt = 0; nt < 8; nt++) {
        int cb = 8 * nt + 2 * t;
        float2 blo = *reinterpret_cast<const float2*>(ats + rlo + cb);
        float2 bhi = *reinterpret_cast<const float2*>(ats + rhi + cb);
        y0 = fmaf(blo.x, d[nt][0], fmaf(blo.y, d[nt][1], y0));
        y1 = fmaf(bhi.x, d[nt][2], fmaf(bhi.y, d[nt][3], y1));
    }

    y0 += __shfl_xor_sync(0xFFFFFFFFu, y0, 1);
    y0 += __shfl_xor_sync(0xFFFFFFFFu, y0, 2);
    y1 += __shfl_xor_sync(0xFFFFFFFFu, y1, 1);
    y1 += __shfl_xor_sync(0xFFFFFFFFu, y1, 2);

    if (t == 0) {
        float bc = fminf(fmaxf(braw[0], -10.0f), 10.0f);
        size_t base = (size_t)bid * ROWS_PER_CTA + rb + g;
        out[base + 0] = y0 + bc;
        out[base + 8] = y1 + bc;
    }
}

extern "C" void kernel_launch(void* const* d_in, const int* in_sizes, int n_in,
                              void* d_out, int out_size)
{
    const float* AT    = (const float*)d_in[0];
    const float* Kraw  = (const float*)d_in[1];
    const float* BTraw = (const float*)d_in[2];
    const float* Wraw  = (const float*)d_in[3];
    const float* braw  = (const float*)d_in[4];
    float* out = (float*)d_out;

    const int B = in_sizes[0] / N_DIM;          // 16384
    const int grid = B / ROWS_PER_CTA;          // 128

    cudaFuncSetAttribute(cnet_mma_kernel,
                         cudaFuncAttributeMaxDynamicSharedMemorySize,
                         SMEM_TOTAL);

    cnet_mma_kernel<<<grid, THREADS, SMEM_TOTAL>>>(
        AT, Kraw, BTraw, Wraw, braw, out);
}

// round 15
// speedup vs baseline: 1.6839x; 1.6839x over previous
#include <cuda_runtime.h>
#include <cuda_fp16.h>
#include <cstdint>
#include <cstddef>

// CompetitiveNetwork via mma.sync (m16n8k16 f16 operands, fp32 accum).
// R14: revert R13's f16-accumulate MMA (tensor-cycles rose 60% -> slower on
// sm_103a). Base = R12 (proven 37.3us). Change: cheap-phase nonlinearity in
// packed half2 -- pack d to fp16 pairs FIRST (needed for A-frags anyway),
// then h2rcp on the pair (1 MUFU per 2 elems; output IS the A-frag) and
// hmul2 with register-cached half2 AT for AF-steps. Halves MUFU pressure
// and cuts ~104 issue slots per cheap iteration. Error is truncation-
// dominated (proven), so the fp16 pass-through before rcp is free.
// Schedule: 15 cheap + 2 precise pairs + final precise BF.

#define THREADS 256
#define ROWS_PER_CTA 128
#define N_DIM 64
#define CHEAP_ITERS 15

typedef unsigned int u32;

#define MATS_BYTES (6 * 8192)              // fragment-ordered split matrices
#define AT_OFF     MATS_BYTES
#define AT_STRIDE  66
#define SMEM_TOTAL (AT_OFF + 128 * AT_STRIDE * 4)   // 82944

__device__ __forceinline__ float rcpa(float x) {
    float r; asm("rcp.approx.f32 %0, %1;" : "=f"(r) : "f"(x)); return r;
}
__device__ __forceinline__ u32 packh2(float x0, float x1) {
    __half2 h = __floats2half2_rn(x0, x1);
    return *reinterpret_cast<u32*>(&h);
}
__device__ __forceinline__ void split2h(float x0, float x1, u32 &hi, u32 &lo) {
    __half2 h = __floats2half2_rn(x0, x1);
    hi = *reinterpret_cast<u32*>(&h);
    float h0 = __low2float(h), h1 = __high2float(h);
    __half2 l = __floats2half2_rn(x0 - h0, x1 - h1);
    lo = *reinterpret_cast<u32*>(&l);
}
__device__ __forceinline__ u32 h2rcp_u(u32 x) {
    __half2 v = h2rcp(*reinterpret_cast<__half2*>(&x));
    return *reinterpret_cast<u32*>(&v);
}
__device__ __forceinline__ u32 hmul2_u(u32 a, u32 b) {
    __half2 r = __hmul2(*reinterpret_cast<__half2*>(&a),
                        *reinterpret_cast<__half2*>(&b));
    return *reinterpret_cast<u32*>(&r);
}

// fragment-order store: element at logical (k, n) of a B operand
__device__ __forceinline__ void st_frag(__half* base, int k, int n, __half v) {
    int lane = ((n & 7) << 2) | ((k & 7) >> 1);
    int w2   = (((k >> 4) & 1) << 1) | ((k >> 3) & 1);
    int idx  = ((k >> 5) << 11) | ((n >> 3) << 8) | (lane << 3)
             | (w2 << 1) | (k & 1);
    base[idx] = v;
}

#define MMA(d, a, b0, b1)                                                      \
    asm("mma.sync.aligned.m16n8k16.row.col.f32.f16.f16.f32 "                   \
        "{%0,%1,%2,%3}, {%4,%5,%6,%7}, {%8,%9}, {%0,%1,%2,%3};"                \
        : "+f"((d)[0]), "+f"((d)[1]), "+f"((d)[2]), "+f"((d)[3])               \
        : "r"((a)[0]), "r"((a)[1]), "r"((a)[2]), "r"((a)[3]),                  \
          "r"(b0), "r"(b1))

// first MMA of an accumulator, C = 0 (epilogue H: no bias)
#define MMA_Z(d, a, b0, b1)                                                    \
    asm("mma.sync.aligned.m16n8k16.row.col.f32.f16.f16.f32 "                   \
        "{%0,%1,%2,%3}, {%4,%5,%6,%7}, {%8,%9}, {%10,%10,%10,%10};"            \
        : "=f"((d)[0]), "=f"((d)[1]), "=f"((d)[2]), "=f"((d)[3])               \
        : "r"((a)[0]), "r"((a)[1]), "r"((a)[2]), "r"((a)[3]),                  \
          "r"(b0), "r"(b1), "f"(0.0f))

// first MMA of an accumulator, C = 1 (folds the "+1.0" of the nonlinearity)
#define MMA_ONE(d, a, b0, b1)                                                  \
    asm("mma.sync.aligned.m16n8k16.row.col.f32.f16.f16.f32 "                   \
        "{%0,%1,%2,%3}, {%4,%5,%6,%7}, {%8,%9}, {%10,%10,%10,%10};"            \
        : "=f"((d)[0]), "=f"((d)[1]), "=f"((d)[2]), "=f"((d)[3])               \
        : "r"((a)[0]), "r"((a)[1]), "r"((a)[2]), "r"((a)[3]),                  \
          "r"(b0), "r"(b1), "f"(1.0f))

__global__ void __launch_bounds__(THREADS, 1)
cnet_mma_kernel(const float* __restrict__ AT,
                const float* __restrict__ Kraw,
                const float* __restrict__ BTraw,
                const float* __restrict__ Wraw,
                const float* __restrict__ braw,
                float* __restrict__ out)
{
    extern __shared__ char smc[];
    __half* mats = reinterpret_cast<__half*>(smc);
    float* ats = reinterpret_cast<float*>(smc + AT_OFF);   // [128][66] f32

    const int tid  = threadIdx.x;
    const int w    = tid >> 5;          // warp 0..7 -> rows [16w, 16w+16)
    const int lane = tid & 31;
    const int g    = lane >> 2;
    const int t    = lane & 3;
    const int rb   = w * 16;
    const int bid  = blockIdx.x;

    // ---- setup: exp/clip K, bt-folded fragment-ordered split matrices ------
    // mats 0/1: KT hi/lo   B(k=i,n=j) = K[i][j]           (BF-step)
    // mats 2/3: K'  hi/lo  B(k=j,n=i) = K[i][j]*bt[j]     (AF-step)
    // mats 4/5: M'  hi/lo  B(k=i,n=j) = K[i][j]*W*bt[j]   (epilogue)
    for (int idx = tid; idx < 4096; idx += THREADS) {
        int i = idx >> 6, j = idx & 63;
        float k = fminf(__expf(Kraw[idx]), 1000.0f);
        float btj = fminf(__expf(BTraw[j]), 1000.0f);
        float wv = fminf(fmaxf(Wraw[idx], -10.0f), 10.0f);
        float kp = k * btj;
        float m  = k * wv * btj;
        __half kh = __float2half_rn(k);
        __half kl = __float2half_rn(k - __half2float(kh));
        __half ph = __float2half_rn(kp);
        __half pl = __float2half_rn(kp - __half2float(ph));
        __half mh = __float2half_rn(m);
        __half ml = __float2half_rn(m - __half2float(mh));
        st_frag(mats + 0 * 4096, i, j, kh);
        st_frag(mats + 1 * 4096, i, j, kl);
        st_frag(mats + 2 * 4096, j, i, ph);
        st_frag(mats + 3 * 4096, j, i, pl);
        st_frag(mats + 4 * 4096, i, j, mh);
        st_frag(mats + 5 * 4096, i, j, ml);
    }
    {
        const float4* atg = reinterpret_cast<const float4*>(
            AT + (size_t)bid * (ROWS_PER_CTA * N_DIM));
        for (int idx = tid; idx < 2048; idx += THREADS) {
            float4 v = atg[idx];
            int r = idx >> 4, c = (idx & 15) << 2;
            float* p = ats + r * AT_STRIDE + c;
            p[0] = v.x; p[1] = v.y; p[2] = v.z; p[3] = v.w;
        }
    }
    __syncthreads();

    const int rlo = (rb + g) * AT_STRIDE;
    const int rhi = (rb + 8 + g) * AT_STRIDE;

    // ---- AT cached as half2 pairs for cheap AF nonlinearity -----------------
    // atc2[nt][0] = (AT[g, 8nt+2t], AT[g, 8nt+2t+1]); [1] = row g+8
    u32 atc2[8][2];
    #pragma unroll
    for (int nt = 0; nt < 8; nt++) {
        int cb = 8 * nt + 2 * t;
        float2 plo = *reinterpret_cast<const float2*>(ats + rlo + cb);
        float2 phi = *reinterpret_cast<const float2*>(ats + rhi + cb);
        atc2[nt][0] = packh2(plo.x, plo.y);
        atc2[nt][1] = packh2(phi.x, phi.y);
    }

    // ---- fragment registers --------------------------------------------------
    float d[8][4];            // D frags: [nt][c]
    u32 ah[4][4], al[4][4];   // A frags hi/lo

    // initial A = fp16(AT)  (mapping: ah[kt] <- atc2[2kt], atc2[2kt+1])
    #pragma unroll
    for (int kt = 0; kt < 4; kt++) {
        ah[kt][0] = atc2[2*kt][0];
        ah[kt][1] = atc2[2*kt][1];
        ah[kt][2] = atc2[2*kt+1][0];
        ah[kt][3] = atc2[2*kt+1][1];
    }

    const uint4* __restrict__ frag = reinterpret_cast<const uint4*>(smc) + lane;

    // cheap matvec: d = A_hi @ B_hi + 1   (fp32 accumulate)
#define MMA_PHASE_CHEAP(MH)                                                    \
    do {                                                                       \
        _Pragma("unroll")                                                      \
        for (int nt = 0; nt < 8; nt++) {                                       \
            uint4 h0 = frag[(MH) * 512 +       nt * 32];                       \
            uint4 h1 = frag[(MH) * 512 + 256 + nt * 32];                       \
            MMA_ONE(d[nt], ah[0], h0.x, h0.y);                                 \
            MMA(d[nt], ah[1], h0.z, h0.w);                                     \
            MMA(d[nt], ah[2], h1.x, h1.y);                                     \
            MMA(d[nt], ah[3], h1.z, h1.w);                                     \
        }                                                                      \
    } while (0)

    // cheap BF nonlin + repack: ah = h2rcp(pack(d))  (output IS the A-frag)
#define BF_NONLIN_REPACK_CHEAP()                                               \
    do {                                                                       \
        _Pragma("unroll")                                                      \
        for (int kt = 0; kt < 4; kt++) {                                       \
            ah[kt][0] = h2rcp_u(packh2(d[2*kt][0],   d[2*kt][1]));             \
            ah[kt][1] = h2rcp_u(packh2(d[2*kt][2],   d[2*kt][3]));             \
            ah[kt][2] = h2rcp_u(packh2(d[2*kt+1][0], d[2*kt+1][1]));           \
            ah[kt][3] = h2rcp_u(packh2(d[2*kt+1][2], d[2*kt+1][3]));           \
        }                                                                      \
    } while (0)

    // cheap AF nonlin + repack: ah = AT(h2) * h2rcp(pack(d))
#define AF_NONLIN_REPACK_CHEAP()                                               \
    do {                                                                       \
        _Pragma("unroll")                                                      \
        for (int kt = 0; kt < 4; kt++) {                                       \
            ah[kt][0] = hmul2_u(atc2[2*kt][0],                                 \
                          h2rcp_u(packh2(d[2*kt][0],   d[2*kt][1])));          \
            ah[kt][1] = hmul2_u(atc2[2*kt][1],                                 \
                          h2rcp_u(packh2(d[2*kt][2],   d[2*kt][3])));          \
            ah[kt][2] = hmul2_u(atc2[2*kt+1][0],                               \
                          h2rcp_u(packh2(d[2*kt+1][0], d[2*kt+1][1])));        \
            ah[kt][3] = hmul2_u(atc2[2*kt+1][1],                               \
                          h2rcp_u(packh2(d[2*kt+1][2], d[2*kt+1][3])));        \
        }                                                                      \
    } while (0)

    // full matvec: d = (Ah+Al) @ Bh + Ah @ Bl + BIAS (BIAS = MMA_ONE/MMA_Z)
#define MMA_PHASE_FULL(MH, FIRST)                                              \
    do {                                                                       \
        _Pragma("unroll")                                                      \
        for (int nt = 0; nt < 8; nt++) {                                       \
            uint4 h0 = frag[(MH) * 512 +       nt * 32];                       \
            uint4 h1 = frag[(MH) * 512 + 256 + nt * 32];                       \
            uint4 l0 = frag[((MH)+1) * 512 +       nt * 32];                   \
            uint4 l1 = frag[((MH)+1) * 512 + 256 + nt * 32];                   \
            FIRST(d[nt], ah[0], h0.x, h0.y);                                   \
            MMA(d[nt], al[0], h0.x, h0.y);                                     \
            MMA(d[nt], ah[0], l0.x, l0.y);                                     \
            MMA(d[nt], ah[1], h0.z, h0.w);                                     \
            MMA(d[nt], al[1], h0.z, h0.w);                                     \
            MMA(d[nt], ah[1], l0.z, l0.w);                                     \
            MMA(d[nt], ah[2], h1.x, h1.y);                                     \
            MMA(d[nt], al[2], h1.x, h1.y);                                     \
            MMA(d[nt], ah[2], l1.x, l1.y);                                     \
            MMA(d[nt], ah[3], h1.z, h1.w);                                     \
            MMA(d[nt], al[3], h1.z, h1.w);                                     \
            MMA(d[nt], ah[3], l1.z, l1.w);                                     \
        }                                                                      \
    } while (0)

    // precise nonlinearities (fp32 rcp)
#define BF_NONLIN()                                                            \
    do {                                                                       \
        _Pragma("unroll")                                                      \
        for (int nt = 0; nt < 8; nt++) {                                       \
            d[nt][0] = rcpa(d[nt][0]);                                         \
            d[nt][1] = rcpa(d[nt][1]);                                         \
            d[nt][2] = rcpa(d[nt][2]);                                         \
            d[nt][3] = rcpa(d[nt][3]);                                         \
        }                                                                      \
    } while (0)

#define AF_NONLIN()                                                            \
    do {                                                                       \
        _Pragma("unroll")                                                      \
        for (int nt = 0; nt < 8; nt++) {                                       \
            int cb = 8 * nt + 2 * t;                                           \
            float2 plo = *reinterpret_cast<const float2*>(ats + rlo + cb);     \
            float2 phi = *reinterpret_cast<const float2*>(ats + rhi + cb);     \
            d[nt][0] = plo.x * rcpa(d[nt][0]);                                 \
            d[nt][1] = plo.y * rcpa(d[nt][1]);                                 \
            d[nt][2] = phi.x * rcpa(d[nt][2]);                                 \
            d[nt][3] = phi.y * rcpa(d[nt][3]);                                 \
        }                                                                      \
    } while (0)

#define REPACK_FULL()                                                          \
    do {                                                                       \
        _Pragma("unroll")                                                      \
        for (int kt = 0; kt < 4; kt++) {                                       \
            split2h(d[2*kt][0],   d[2*kt][1],   ah[kt][0], al[kt][0]);         \
            split2h(d[2*kt][2],   d[2*kt][3],   ah[kt][1], al[kt][1]);         \
            split2h(d[2*kt+1][0], d[2*kt+1][1], ah[kt][2], al[kt][2]);         \
            split2h(d[2*kt+1][2], d[2*kt+1][3], ah[kt][3], al[kt][3]);         \
        }                                                                      \
    } while (0)

    // ---- phase 1: 15 cheap iterations ---------------------------------------
    #pragma unroll 1
    for (int it = 0; it < CHEAP_ITERS; ++it) {
        MMA_PHASE_CHEAP(0);        // BF-step: d = KT^T(AF) + 1
        BF_NONLIN_REPACK_CHEAP();  // A <- rcp(d) as fp16 pairs
        MMA_PHASE_CHEAP(2);        // AF-step: d = K'(BF') + 1
        AF_NONLIN_REPACK_CHEAP();  // A <- AT * rcp(d)
    }

    // precision boundary: lo residuals start at zero
    #pragma unroll
    for (int kt = 0; kt < 4; kt++)
        #pragma unroll
        for (int r = 0; r < 4; r++) al[kt][r] = 0u;

    // ---- phase 2: 2 precise BF/AF pairs, then final BF ----------------------
    #pragma unroll 1
    for (int it = 0; it < 2; ++it) {
        MMA_PHASE_FULL(0, MMA_ONE);
        BF_NONLIN();
        REPACK_FULL();
        MMA_PHASE_FULL(2, MMA_ONE);
        AF_NONLIN();
        REPACK_FULL();
    }

    // final BF step: keep fp32 BF' for the output contraction
    MMA_PHASE_FULL(0, MMA_ONE);
    BF_NONLIN();

    // stash final BF' (fp32) into the AT region (AT dead; same-lane rw)
    #pragma unroll
    for (int nt = 0; nt < 8; nt++) {
        int cb = 8 * nt + 2 * t;
        *reinterpret_cast<float2*>(ats + rlo + cb) =
            make_float2(d[nt][0], d[nt][1]);
        *reinterpret_cast<float2*>(ats + rhi + cb) =
            make_float2(d[nt][2], d[nt][3]);
    }

    // epilogue: H = AF @ M' (C = 0); y = sum_j BF'_j H_j
    MMA_PHASE_FULL(4, MMA_Z);

    float y0 = 0.f, y1 = 0.f;
    #pragma unroll
    for (int nt = 0; nt < 8; nt++) {
        int cb = 8 * nt + 2 * t;
        float2 blo = *reinterpret_cast<const float2*>(ats + rlo + cb);
        float2 bhi = *reinterpret_cast<const float2*>(ats + rhi + cb);
        y0 = fmaf(blo.x, d[nt][0], fmaf(blo.y, d[nt][1], y0));
        y1 = fmaf(bhi.x, d[nt][2], fmaf(bhi.y, d[nt][3], y1));
    }

    y0 += __shfl_xor_sync(0xFFFFFFFFu, y0, 1);
    y0 += __shfl_xor_sync(0xFFFFFFFFu, y0, 2);
    y1 += __shfl_xor_sync(0xFFFFFFFFu, y1, 1);
    y1 += __shfl_xor_sync(0xFFFFFFFFu, y1, 2);

    if (t == 0) {
        float bc = fminf(fmaxf(braw[0], -10.0f), 10.0f);
        size_t base = (size_t)bid * ROWS_PER_CTA + rb + g;
        out[base + 0] = y0 + bc;
        out[base + 8] = y1 + bc;
    }
}

extern "C" void kernel_launch(void* const* d_in, const int* in_sizes, int n_in,
                              void* d_out, int out_size)
{
    const float* AT    = (const float*)d_in[0];
    const float* Kraw  = (const float*)d_in[1];
    const float* BTraw = (const float*)d_in[2];
    const float* Wraw  = (const float*)d_in[3];
    const float* braw  = (const float*)d_in[4];
    float* out = (float*)d_out;

    const int B = in_sizes[0] / N_DIM;          // 16384
    const int grid = B / ROWS_PER_CTA;          // 128

    cudaFuncSetAttribute(cnet_mma_kernel,
                         cudaFuncAttributeMaxDynamicSharedMemorySize,
                         SMEM_TOTAL);

    cnet_mma_kernel<<<grid, THREADS, SMEM_TOTAL>>>(
        AT, Kraw, BTraw, Wraw, braw, out);
}

// round 16
// speedup vs baseline: 1.8892x; 1.1220x over previous
#include <cuda_runtime.h>
#include <cuda_fp16.h>
#include <cstdint>
#include <cstddef>

// CompetitiveNetwork via mma.sync (m16n8k16 f16 operands, fp32 accum).
// R15: schedule compression at the precise end. Error model (calibrated over
// R5/R6/R7/R12): truncation rho~0.54/step, cheap arithmetic noise <2.7e-3
// contracted by the precise tail. 15 cheap + ONE precise pair + final
// precise BF (17 BF-steps) => predicted rel_err ~2.5-3e-4 (threshold 1e-3).
// Saves 2 full matvecs (2x96 HMMA) + 2 full repacks vs R14.
// Cheap-phase nonlinearity in packed half2 (h2rcp/hmul2), bt folded into
// matrices, +1 folded into accumulator init. 8 warps/CTA, 16 rows/warp,
// state in registers, no syncs in the loop.

#define THREADS 256
#define ROWS_PER_CTA 128
#define N_DIM 64
#define CHEAP_ITERS 15

typedef unsigned int u32;

#define MATS_BYTES (6 * 8192)              // fragment-ordered split matrices
#define AT_OFF     MATS_BYTES
#define AT_STRIDE  66
#define SMEM_TOTAL (AT_OFF + 128 * AT_STRIDE * 4)   // 82944

__device__ __forceinline__ float rcpa(float x) {
    float r; asm("rcp.approx.f32 %0, %1;" : "=f"(r) : "f"(x)); return r;
}
__device__ __forceinline__ u32 packh2(float x0, float x1) {
    __half2 h = __floats2half2_rn(x0, x1);
    return *reinterpret_cast<u32*>(&h);
}
__device__ __forceinline__ void split2h(float x0, float x1, u32 &hi, u32 &lo) {
    __half2 h = __floats2half2_rn(x0, x1);
    hi = *reinterpret_cast<u32*>(&h);
    float h0 = __low2float(h), h1 = __high2float(h);
    __half2 l = __floats2half2_rn(x0 - h0, x1 - h1);
    lo = *reinterpret_cast<u32*>(&l);
}
__device__ __forceinline__ u32 h2rcp_u(u32 x) {
    __half2 v = h2rcp(*reinterpret_cast<__half2*>(&x));
    return *reinterpret_cast<u32*>(&v);
}
__device__ __forceinline__ u32 hmul2_u(u32 a, u32 b) {
    __half2 r = __hmul2(*reinterpret_cast<__half2*>(&a),
                        *reinterpret_cast<__half2*>(&b));
    return *reinterpret_cast<u32*>(&r);
}

// fragment-order store: element at logical (k, n) of a B operand
__device__ __forceinline__ void st_frag(__half* base, int k, int n, __half v) {
    int lane = ((n & 7) << 2) | ((k & 7) >> 1);
    int w2   = (((k >> 4) & 1) << 1) | ((k >> 3) & 1);
    int idx  = ((k >> 5) << 11) | ((n >> 3) << 8) | (lane << 3)
             | (w2 << 1) | (k & 1);
    base[idx] = v;
}

#define MMA(d, a, b0, b1)                                                      \
    asm("mma.sync.aligned.m16n8k16.row.col.f32.f16.f16.f32 "                   \
        "{%0,%1,%2,%3}, {%4,%5,%6,%7}, {%8,%9}, {%0,%1,%2,%3};"                \
        : "+f"((d)[0]), "+f"((d)[1]), "+f"((d)[2]), "+f"((d)[3])               \
        : "r"((a)[0]), "r"((a)[1]), "r"((a)[2]), "r"((a)[3]),                  \
          "r"(b0), "r"(b1))

// first MMA of an accumulator, C = 0 (epilogue H: no bias)
#define MMA_Z(d, a, b0, b1)                                                    \
    asm("mma.sync.aligned.m16n8k16.row.col.f32.f16.f16.f32 "                   \
        "{%0,%1,%2,%3}, {%4,%5,%6,%7}, {%8,%9}, {%10,%10,%10,%10};"            \
        : "=f"((d)[0]), "=f"((d)[1]), "=f"((d)[2]), "=f"((d)[3])               \
        : "r"((a)[0]), "r"((a)[1]), "r"((a)[2]), "r"((a)[3]),                  \
          "r"(b0), "r"(b1), "f"(0.0f))

// first MMA of an accumulator, C = 1 (folds the "+1.0" of the nonlinearity)
#define MMA_ONE(d, a, b0, b1)                                                  \
    asm("mma.sync.aligned.m16n8k16.row.col.f32.f16.f16.f32 "                   \
        "{%0,%1,%2,%3}, {%4,%5,%6,%7}, {%8,%9}, {%10,%10,%10,%10};"            \
        : "=f"((d)[0]), "=f"((d)[1]), "=f"((d)[2]), "=f"((d)[3])               \
        : "r"((a)[0]), "r"((a)[1]), "r"((a)[2]), "r"((a)[3]),                  \
          "r"(b0), "r"(b1), "f"(1.0f))

__global__ void __launch_bounds__(THREADS, 1)
cnet_mma_kernel(const float* __restrict__ AT,
                const float* __restrict__ Kraw,
                const float* __restrict__ BTraw,
                const float* __restrict__ Wraw,
                const float* __restrict__ braw,
                float* __restrict__ out)
{
    extern __shared__ char smc[];
    __half* mats = reinterpret_cast<__half*>(smc);
    float* ats = reinterpret_cast<float*>(smc + AT_OFF);   // [128][66] f32

    const int tid  = threadIdx.x;
    const int w    = tid >> 5;          // warp 0..7 -> rows [16w, 16w+16)
    const int lane = tid & 31;
    const int g    = lane >> 2;
    const int t    = lane & 3;
    const int rb   = w * 16;
    const int bid  = blockIdx.x;

    // ---- setup: exp/clip K, bt-folded fragment-ordered split matrices ------
    // mats 0/1: KT hi/lo   B(k=i,n=j) = K[i][j]           (BF-step)
    // mats 2/3: K'  hi/lo  B(k=j,n=i) = K[i][j]*bt[j]     (AF-step)
    // mats 4/5: M'  hi/lo  B(k=i,n=j) = K[i][j]*W*bt[j]   (epilogue)
    for (int idx = tid; idx < 4096; idx += THREADS) {
        int i = idx >> 6, j = idx & 63;
        float k = fminf(__expf(Kraw[idx]), 1000.0f);
        float btj = fminf(__expf(BTraw[j]), 1000.0f);
        float wv = fminf(fmaxf(Wraw[idx], -10.0f), 10.0f);
        float kp = k * btj;
        float m  = k * wv * btj;
        __half kh = __float2half_rn(k);
        __half kl = __float2half_rn(k - __half2float(kh));
        __half ph = __float2half_rn(kp);
        __half pl = __float2half_rn(kp - __half2float(ph));
        __half mh = __float2half_rn(m);
        __half ml = __float2half_rn(m - __half2float(mh));
        st_frag(mats + 0 * 4096, i, j, kh);
        st_frag(mats + 1 * 4096, i, j, kl);
        st_frag(mats + 2 * 4096, j, i, ph);
        st_frag(mats + 3 * 4096, j, i, pl);
        st_frag(mats + 4 * 4096, i, j, mh);
        st_frag(mats + 5 * 4096, i, j, ml);
    }
    {
        const float4* atg = reinterpret_cast<const float4*>(
            AT + (size_t)bid * (ROWS_PER_CTA * N_DIM));
        for (int idx = tid; idx < 2048; idx += THREADS) {
            float4 v = atg[idx];
            int r = idx >> 4, c = (idx & 15) << 2;
            float* p = ats + r * AT_STRIDE + c;
            p[0] = v.x; p[1] = v.y; p[2] = v.z; p[3] = v.w;
        }
    }
    __syncthreads();

    const int rlo = (rb + g) * AT_STRIDE;
    const int rhi = (rb + 8 + g) * AT_STRIDE;

    // ---- AT cached as half2 pairs for cheap AF nonlinearity -----------------
    u32 atc2[8][2];
    #pragma unroll
    for (int nt = 0; nt < 8; nt++) {
        int cb = 8 * nt + 2 * t;
        float2 plo = *reinterpret_cast<const float2*>(ats + rlo + cb);
        float2 phi = *reinterpret_cast<const float2*>(ats + rhi + cb);
        atc2[nt][0] = packh2(plo.x, plo.y);
        atc2[nt][1] = packh2(phi.x, phi.y);
    }

    // ---- fragment registers --------------------------------------------------
    float d[8][4];            // D frags: [nt][c]
    u32 ah[4][4], al[4][4];   // A frags hi/lo

    // initial A = fp16(AT)
    #pragma unroll
    for (int kt = 0; kt < 4; kt++) {
        ah[kt][0] = atc2[2*kt][0];
        ah[kt][1] = atc2[2*kt][1];
        ah[kt][2] = atc2[2*kt+1][0];
        ah[kt][3] = atc2[2*kt+1][1];
    }

    const uint4* __restrict__ frag = reinterpret_cast<const uint4*>(smc) + lane;

    // cheap matvec: d = A_hi @ B_hi + 1   (fp32 accumulate)
#define MMA_PHASE_CHEAP(MH)                                                    \
    do {                                                                       \
        _Pragma("unroll")                                                      \
        for (int nt = 0; nt < 8; nt++) {                                       \
            uint4 h0 = frag[(MH) * 512 +       nt * 32];                       \
            uint4 h1 = frag[(MH) * 512 + 256 + nt * 32];                       \
            MMA_ONE(d[nt], ah[0], h0.x, h0.y);                                 \
            MMA(d[nt], ah[1], h0.z, h0.w);                                     \
            MMA(d[nt], ah[2], h1.x, h1.y);                                     \
            MMA(d[nt], ah[3], h1.z, h1.w);                                     \
        }                                                                      \
    } while (0)

    // cheap BF nonlin + repack: ah = h2rcp(pack(d))
#define BF_NONLIN_REPACK_CHEAP()                                               \
    do {                                                                       \
        _Pragma("unroll")                                                      \
        for (int kt = 0; kt < 4; kt++) {                                       \
            ah[kt][0] = h2rcp_u(packh2(d[2*kt][0],   d[2*kt][1]));             \
            ah[kt][1] = h2rcp_u(packh2(d[2*kt][2],   d[2*kt][3]));             \
            ah[kt][2] = h2rcp_u(packh2(d[2*kt+1][0], d[2*kt+1][1]));           \
            ah[kt][3] = h2rcp_u(packh2(d[2*kt+1][2], d[2*kt+1][3]));           \
        }                                                                      \
    } while (0)

    // cheap AF nonlin + repack: ah = AT(h2) * h2rcp(pack(d))
#define AF_NONLIN_REPACK_CHEAP()                                               \
    do {                                                                       \
        _Pragma("unroll")                                                      \
        for (int kt = 0; kt < 4; kt++) {                                       \
            ah[kt][0] = hmul2_u(atc2[2*kt][0],                                 \
                          h2rcp_u(packh2(d[2*kt][0],   d[2*kt][1])));          \
            ah[kt][1] = hmul2_u(atc2[2*kt][1],                                 \
                          h2rcp_u(packh2(d[2*kt][2],   d[2*kt][3])));          \
            ah[kt][2] = hmul2_u(atc2[2*kt+1][0],                               \
                          h2rcp_u(packh2(d[2*kt+1][0], d[2*kt+1][1])));        \
            ah[kt][3] = hmul2_u(atc2[2*kt+1][1],                               \
                          h2rcp_u(packh2(d[2*kt+1][2], d[2*kt+1][3])));        \
        }                                                                      \
    } while (0)

    // full matvec: d = (Ah+Al) @ Bh + Ah @ Bl + BIAS (BIAS = MMA_ONE/MMA_Z)
#define MMA_PHASE_FULL(MH, FIRST)                                              \
    do {                                                                       \
        _Pragma("unroll")                                                      \
        for (int nt = 0; nt < 8; nt++) {                                       \
            uint4 h0 = frag[(MH) * 512 +       nt * 32];                       \
            uint4 h1 = frag[(MH) * 512 + 256 + nt * 32];                       \
            uint4 l0 = frag[((MH)+1) * 512 +       nt * 32];                   \
            uint4 l1 = frag[((MH)+1) * 512 + 256 + nt * 32];                   \
            FIRST(d[nt], ah[0], h0.x, h0.y);                                   \
            MMA(d[nt], al[0], h0.x, h0.y);                                     \
            MMA(d[nt], ah[0], l0.x, l0.y);                                     \
            MMA(d[nt], ah[1], h0.z, h0.w);                                     \
            MMA(d[nt], al[1], h0.z, h0.w);                                     \
            MMA(d[nt], ah[1], l0.z, l0.w);                                     \
            MMA(d[nt], ah[2], h1.x, h1.y);                                     \
            MMA(d[nt], al[2], h1.x, h1.y);                                     \
            MMA(d[nt], ah[2], l1.x, l1.y);                                     \
            MMA(d[nt], ah[3], h1.z, h1.w);                                     \
            MMA(d[nt], al[3], h1.z, h1.w);                                     \
            MMA(d[nt], ah[3], l1.z, l1.w);                                     \
        }                                                                      \
    } while (0)

    // precise nonlinearities (fp32 rcp)
#define BF_NONLIN()                                                            \
    do {                                                                       \
        _Pragma("unroll")                                                      \
        for (int nt = 0; nt < 8; nt++) {                                       \
            d[nt][0] = rcpa(d[nt][0]);                                         \
            d[nt][1] = rcpa(d[nt][1]);                                         \
            d[nt][2] = rcpa(d[nt][2]);                                         \
            d[nt][3] = rcpa(d[nt][3]);                                         \
        }                                                                      \
    } while (0)

#define AF_NONLIN()                                                            \
    do {                                                                       \
        _Pragma("unroll")                                                      \
        for (int nt = 0; nt < 8; nt++) {                                       \
            int cb = 8 * nt + 2 * t;                                           \
            float2 plo = *reinterpret_cast<const float2*>(ats + rlo + cb);     \
            float2 phi = *reinterpret_cast<const float2*>(ats + rhi + cb);     \
            d[nt][0] = plo.x * rcpa(d[nt][0]);                                 \
            d[nt][1] = plo.y * rcpa(d[nt][1]);                                 \
            d[nt][2] = phi.x * rcpa(d[nt][2]);                                 \
            d[nt][3] = phi.y * rcpa(d[nt][3]);                                 \
        }                                                                      \
    } while (0)

#define REPACK_FULL()                                                          \
    do {                                                                       \
        _Pragma("unroll")                                                      \
        for (int kt = 0; kt < 4; kt++) {                                       \
            split2h(d[2*kt][0],   d[2*kt][1],   ah[kt][0], al[kt][0]);         \
            split2h(d[2*kt][2],   d[2*kt][3],   ah[kt][1], al[kt][1]);         \
            split2h(d[2*kt+1][0], d[2*kt+1][1], ah[kt][2], al[kt][2]);         \
            split2h(d[2*kt+1][2], d[2*kt+1][3], ah[kt][3], al[kt][3]);         \
        }                                                                      \
    } while (0)

    // ---- phase 1: 15 cheap iterations ---------------------------------------
    #pragma unroll 1
    for (int it = 0; it < CHEAP_ITERS; ++it) {
        MMA_PHASE_CHEAP(0);        // BF-step: d = KT^T(AF) + 1
        BF_NONLIN_REPACK_CHEAP();  // A <- rcp(d) as fp16 pairs
        MMA_PHASE_CHEAP(2);        // AF-step: d = K'(BF') + 1
        AF_NONLIN_REPACK_CHEAP();  // A <- AT * rcp(d)
    }

    // precision boundary: lo residuals start at zero
    #pragma unroll
    for (int kt = 0; kt < 4; kt++)
        #pragma unroll
        for (int r = 0; r < 4; r++) al[kt][r] = 0u;

    // ---- phase 2: ONE precise BF/AF pair, then final precise BF -------------
    MMA_PHASE_FULL(0, MMA_ONE);   // precise BF
    BF_NONLIN();
    REPACK_FULL();
    MMA_PHASE_FULL(2, MMA_ONE);   // precise AF
    AF_NONLIN();
    REPACK_FULL();

    // final BF step: keep fp32 BF' for the output contraction
    MMA_PHASE_FULL(0, MMA_ONE);
    BF_NONLIN();

    // stash final BF' (fp32) into the AT region (AT dead; same-lane rw)
    #pragma unroll
    for (int nt = 0; nt < 8; nt++) {
        int cb = 8 * nt + 2 * t;
        *reinterpret_cast<float2*>(ats + rlo + cb) =
            make_float2(d[nt][0], d[nt][1]);
        *reinterpret_cast<float2*>(ats + rhi + cb) =
            make_float2(d[nt][2], d[nt][3]);
    }

    // epilogue: H = AF @ M' (C = 0); y = sum_j BF'_j H_j
    MMA_PHASE_FULL(4, MMA_Z);

    float y0 = 0.f, y1 = 0.f;
    #pragma unroll
    for (int nt = 0; nt < 8; nt++) {
        int cb = 8 * nt + 2 * t;
        float2 blo = *reinterpret_cast<const float2*>(ats + rlo + cb);
        float2 bhi = *reinterpret_cast<const float2*>(ats + rhi + cb);
        y0 = fmaf(blo.x, d[nt][0], fmaf(blo.y, d[nt][1], y0));
        y1 = fmaf(bhi.x, d[nt][2], fmaf(bhi.y, d[nt][3], y1));
    }

    y0 += __shfl_xor_sync(0xFFFFFFFFu, y0, 1);
    y0 += __shfl_xor_sync(0xFFFFFFFFu, y0, 2);
    y1 += __shfl_xor_sync(0xFFFFFFFFu, y1, 1);
    y1 += __shfl_xor_sync(0xFFFFFFFFu, y1, 2);

    if (t == 0) {
        float bc = fminf(fmaxf(braw[0], -10.0f), 10.0f);
        size_t base = (size_t)bid * ROWS_PER_CTA + rb + g;
        out[base + 0] = y0 + bc;
        out[base + 8] = y1 + bc;
    }
}

extern "C" void kernel_launch(void* const* d_in, const int* in_sizes, int n_in,
                              void* d_out, int out_size)
{
    const float* AT    = (const float*)d_in[0];
    const float* Kraw  = (const float*)d_in[1];
    const float* BTraw = (const float*)d_in[2];
    const float* Wraw  = (const float*)d_in[3];
    const float* braw  = (const float*)d_in[4];
    float* out = (float*)d_out;

    const int B = in_sizes[0] / N_DIM;          // 16384
    const int grid = B / ROWS_PER_CTA;          // 128

    cudaFuncSetAttribute(cnet_mma_kernel,
                         cudaFuncAttributeMaxDynamicSharedMemorySize,
                         SMEM_TOTAL);

    cnet_mma_kernel<<<grid, THREADS, SMEM_TOTAL>>>(
        AT, Kraw, BTraw, Wraw, braw, out);
}

// round 17
// speedup vs baseline: 2.0429x; 1.0813x over previous
#include <cuda_runtime.h>
#include <cuda_fp16.h>
#include <cstdint>
#include <cstddef>

// CompetitiveNetwork via mma.sync (m16n8k16 f16 operands, fp32 accum).
// R16 (base R15):
//  (1) First precise BF uses a 2-term matvec (al == 0 at the boundary, so
//      its 32 al-MMAs were multiplying zeros) -> -32 HMMA, bit-identical.
//      al-zeroing removed (al first written by REPACK_FULL before any read).
//  (2) 14 cheap iterations (was 15): calibrated truncation model
//      (rho~0.51/BF-step; R6 18-step 1.215e-4, R15 17-step 2.37e-4)
//      predicts rel_err ~4.6e-4 at 16 BF-steps, 2.2x under threshold.
// Schedule: 14 cheap + 1 precise pair + final precise BF + epilogue.
// Cheap nonlinearity in packed half2 (h2rcp/hmul2); bt folded into the
// matrices; +1 folded into accumulator init. 8 warps/CTA, 16 rows/warp.

#define THREADS 256
#define ROWS_PER_CTA 128
#define N_DIM 64
#define CHEAP_ITERS 14

typedef unsigned int u32;

#define MATS_BYTES (6 * 8192)              // fragment-ordered split matrices
#define AT_OFF     MATS_BYTES
#define AT_STRIDE  66
#define SMEM_TOTAL (AT_OFF + 128 * AT_STRIDE * 4)   // 82944

__device__ __forceinline__ float rcpa(float x) {
    float r; asm("rcp.approx.f32 %0, %1;" : "=f"(r) : "f"(x)); return r;
}
__device__ __forceinline__ u32 packh2(float x0, float x1) {
    __half2 h = __floats2half2_rn(x0, x1);
    return *reinterpret_cast<u32*>(&h);
}
__device__ __forceinline__ void split2h(float x0, float x1, u32 &hi, u32 &lo) {
    __half2 h = __floats2half2_rn(x0, x1);
    hi = *reinterpret_cast<u32*>(&h);
    float h0 = __low2float(h), h1 = __high2float(h);
    __half2 l = __floats2half2_rn(x0 - h0, x1 - h1);
    lo = *reinterpret_cast<u32*>(&l);
}
__device__ __forceinline__ u32 h2rcp_u(u32 x) {
    __half2 v = h2rcp(*reinterpret_cast<__half2*>(&x));
    return *reinterpret_cast<u32*>(&v);
}
__device__ __forceinline__ u32 hmul2_u(u32 a, u32 b) {
    __half2 r = __hmul2(*reinterpret_cast<__half2*>(&a),
                        *reinterpret_cast<__half2*>(&b));
    return *reinterpret_cast<u32*>(&r);
}

// fragment-order store: element at logical (k, n) of a B operand
__device__ __forceinline__ void st_frag(__half* base, int k, int n, __half v) {
    int lane = ((n & 7) << 2) | ((k & 7) >> 1);
    int w2   = (((k >> 4) & 1) << 1) | ((k >> 3) & 1);
    int idx  = ((k >> 5) << 11) | ((n >> 3) << 8) | (lane << 3)
             | (w2 << 1) | (k & 1);
    base[idx] = v;
}

#define MMA(d, a, b0, b1)                                                      \
    asm("mma.sync.aligned.m16n8k16.row.col.f32.f16.f16.f32 "                   \
        "{%0,%1,%2,%3}, {%4,%5,%6,%7}, {%8,%9}, {%0,%1,%2,%3};"                \
        : "+f"((d)[0]), "+f"((d)[1]), "+f"((d)[2]), "+f"((d)[3])               \
        : "r"((a)[0]), "r"((a)[1]), "r"((a)[2]), "r"((a)[3]),                  \
          "r"(b0), "r"(b1))

// first MMA of an accumulator, C = 0 (epilogue H: no bias)
#define MMA_Z(d, a, b0, b1)                                                    \
    asm("mma.sync.aligned.m16n8k16.row.col.f32.f16.f16.f32 "                   \
        "{%0,%1,%2,%3}, {%4,%5,%6,%7}, {%8,%9}, {%10,%10,%10,%10};"            \
        : "=f"((d)[0]), "=f"((d)[1]), "=f"((d)[2]), "=f"((d)[3])               \
        : "r"((a)[0]), "r"((a)[1]), "r"((a)[2]), "r"((a)[3]),                  \
          "r"(b0), "r"(b1), "f"(0.0f))

// first MMA of an accumulator, C = 1 (folds the "+1.0" of the nonlinearity)
#define MMA_ONE(d, a, b0, b1)                                                  \
    asm("mma.sync.aligned.m16n8k16.row.col.f32.f16.f16.f32 "                   \
        "{%0,%1,%2,%3}, {%4,%5,%6,%7}, {%8,%9}, {%10,%10,%10,%10};"            \
        : "=f"((d)[0]), "=f"((d)[1]), "=f"((d)[2]), "=f"((d)[3])               \
        : "r"((a)[0]), "r"((a)[1]), "r"((a)[2]), "r"((a)[3]),                  \
          "r"(b0), "r"(b1), "f"(1.0f))

__global__ void __launch_bounds__(THREADS, 1)
cnet_mma_kernel(const float* __restrict__ AT,
                const float* __restrict__ Kraw,
                const float* __restrict__ BTraw,
                const float* __restrict__ Wraw,
                const float* __restrict__ braw,
                float* __restrict__ out)
{
    extern __shared__ char smc[];
    __half* mats = reinterpret_cast<__half*>(smc);
    float* ats = reinterpret_cast<float*>(smc + AT_OFF);   // [128][66] f32

    const int tid  = threadIdx.x;
    const int w    = tid >> 5;          // warp 0..7 -> rows [16w, 16w+16)
    const int lane = tid & 31;
    const int g    = lane >> 2;
    const int t    = lane & 3;
    const int rb   = w * 16;
    const int bid  = blockIdx.x;

    // ---- setup: exp/clip K, bt-folded fragment-ordered split matrices ------
    // mats 0/1: KT hi/lo   B(k=i,n=j) = K[i][j]           (BF-step)
    // mats 2/3: K'  hi/lo  B(k=j,n=i) = K[i][j]*bt[j]     (AF-step)
    // mats 4/5: M'  hi/lo  B(k=i,n=j) = K[i][j]*W*bt[j]   (epilogue)
    for (int idx = tid; idx < 4096; idx += THREADS) {
        int i = idx >> 6, j = idx & 63;
        float k = fminf(__expf(Kraw[idx]), 1000.0f);
        float btj = fminf(__expf(BTraw[j]), 1000.0f);
        float wv = fminf(fmaxf(Wraw[idx], -10.0f), 10.0f);
        float kp = k * btj;
        float m  = k * wv * btj;
        __half kh = __float2half_rn(k);
        __half kl = __float2half_rn(k - __half2float(kh));
        __half ph = __float2half_rn(kp);
        __half pl = __float2half_rn(kp - __half2float(ph));
        __half mh = __float2half_rn(m);
        __half ml = __float2half_rn(m - __half2float(mh));
        st_frag(mats + 0 * 4096, i, j, kh);
        st_frag(mats + 1 * 4096, i, j, kl);
        st_frag(mats + 2 * 4096, j, i, ph);
        st_frag(mats + 3 * 4096, j, i, pl);
        st_frag(mats + 4 * 4096, i, j, mh);
        st_frag(mats + 5 * 4096, i, j, ml);
    }
    {
        const float4* atg = reinterpret_cast<const float4*>(
            AT + (size_t)bid * (ROWS_PER_CTA * N_DIM));
        for (int idx = tid; idx < 2048; idx += THREADS) {
            float4 v = atg[idx];
            int r = idx >> 4, c = (idx & 15) << 2;
            float* p = ats + r * AT_STRIDE + c;
            p[0] = v.x; p[1] = v.y; p[2] = v.z; p[3] = v.w;
        }
    }
    __syncthreads();

    const int rlo = (rb + g) * AT_STRIDE;
    const int rhi = (rb + 8 + g) * AT_STRIDE;

    // ---- AT cached as half2 pairs for cheap AF nonlinearity -----------------
    u32 atc2[8][2];
    #pragma unroll
    for (int nt = 0; nt < 8; nt++) {
        int cb = 8 * nt + 2 * t;
        float2 plo = *reinterpret_cast<const float2*>(ats + rlo + cb);
        float2 phi = *reinterpret_cast<const float2*>(ats + rhi + cb);
        atc2[nt][0] = packh2(plo.x, plo.y);
        atc2[nt][1] = packh2(phi.x, phi.y);
    }

    // ---- fragment registers --------------------------------------------------
    float d[8][4];            // D frags: [nt][c]
    u32 ah[4][4], al[4][4];   // A frags hi/lo

    // initial A = fp16(AT)
    #pragma unroll
    for (int kt = 0; kt < 4; kt++) {
        ah[kt][0] = atc2[2*kt][0];
        ah[kt][1] = atc2[2*kt][1];
        ah[kt][2] = atc2[2*kt+1][0];
        ah[kt][3] = atc2[2*kt+1][1];
    }

    const uint4* __restrict__ frag = reinterpret_cast<const uint4*>(smc) + lane;

    // cheap matvec: d = A_hi @ B_hi + 1   (fp32 accumulate)
#define MMA_PHASE_CHEAP(MH)                                                    \
    do {                                                                       \
        _Pragma("unroll")                                                      \
        for (int nt = 0; nt < 8; nt++) {                                       \
            uint4 h0 = frag[(MH) * 512 +       nt * 32];                       \
            uint4 h1 = frag[(MH) * 512 + 256 + nt * 32];                       \
            MMA_ONE(d[nt], ah[0], h0.x, h0.y);                                 \
            MMA(d[nt], ah[1], h0.z, h0.w);                                     \
            MMA(d[nt], ah[2], h1.x, h1.y);                                     \
            MMA(d[nt], ah[3], h1.z, h1.w);                                     \
        }                                                                      \
    } while (0)

    // cheap BF nonlin + repack: ah = h2rcp(pack(d))
#define BF_NONLIN_REPACK_CHEAP()                                               \
    do {                                                                       \
        _Pragma("unroll")                                                      \
        for (int kt = 0; kt < 4; kt++) {                                       \
            ah[kt][0] = h2rcp_u(packh2(d[2*kt][0],   d[2*kt][1]));             \
            ah[kt][1] = h2rcp_u(packh2(d[2*kt][2],   d[2*kt][3]));             \
            ah[kt][2] = h2rcp_u(packh2(d[2*kt+1][0], d[2*kt+1][1]));           \
            ah[kt][3] = h2rcp_u(packh2(d[2*kt+1][2], d[2*kt+1][3]));           \
        }                                                                      \
    } while (0)

    // cheap AF nonlin + repack: ah = AT(h2) * h2rcp(pack(d))
#define AF_NONLIN_REPACK_CHEAP()                                               \
    do {                                                                       \
        _Pragma("unroll")                                                      \
        for (int kt = 0; kt < 4; kt++) {                                       \
            ah[kt][0] = hmul2_u(atc2[2*kt][0],                                 \
                          h2rcp_u(packh2(d[2*kt][0],   d[2*kt][1])));          \
            ah[kt][1] = hmul2_u(atc2[2*kt][1],                                 \
                          h2rcp_u(packh2(d[2*kt][2],   d[2*kt][3])));          \
            ah[kt][2] = hmul2_u(atc2[2*kt+1][0],                               \
                          h2rcp_u(packh2(d[2*kt+1][0], d[2*kt+1][1])));        \
            ah[kt][3] = hmul2_u(atc2[2*kt+1][1],                               \
                          h2rcp_u(packh2(d[2*kt+1][2], d[2*kt+1][3])));        \
        }                                                                      \
    } while (0)

    // full matvec: d = (Ah+Al) @ Bh + Ah @ Bl + BIAS (BIAS = MMA_ONE/MMA_Z)
#define MMA_PHASE_FULL(MH, FIRST)                                              \
    do {                                                                       \
        _Pragma("unroll")                                                      \
        for (int nt = 0; nt < 8; nt++) {                                       \
            uint4 h0 = frag[(MH) * 512 +       nt * 32];                       \
            uint4 h1 = frag[(MH) * 512 + 256 + nt * 32];                       \
            uint4 l0 = frag[((MH)+1) * 512 +       nt * 32];                   \
            uint4 l1 = frag[((MH)+1) * 512 + 256 + nt * 32];                   \
            FIRST(d[nt], ah[0], h0.x, h0.y);                                   \
            MMA(d[nt], al[0], h0.x, h0.y);                                     \
            MMA(d[nt], ah[0], l0.x, l0.y);                                     \
            MMA(d[nt], ah[1], h0.z, h0.w);                                     \
            MMA(d[nt], al[1], h0.z, h0.w);                                     \
            MMA(d[nt], ah[1], l0.z, l0.w);                                     \
            MMA(d[nt], ah[2], h1.x, h1.y);                                     \
            MMA(d[nt], al[2], h1.x, h1.y);                                     \
            MMA(d[nt], ah[2], l1.x, l1.y);                                     \
            MMA(d[nt], ah[3], h1.z, h1.w);                                     \
            MMA(d[nt], al[3], h1.z, h1.w);                                     \
            MMA(d[nt], ah[3], l1.z, l1.w);                                     \
        }                                                                      \
    } while (0)

    // 2-term full matvec for the al==0 boundary step: d = Ah@Bh + Ah@Bl + 1
    // (exactly equal to the 3-term form when al = 0; 64 HMMA instead of 96)
#define MMA_PHASE_FULL_NOAL(MH)                                                \
    do {                                                                       \
        _Pragma("unroll")                                                      \
        for (int nt = 0; nt < 8; nt++) {                                       \
            uint4 h0 = frag[(MH) * 512 +       nt * 32];                       \
            uint4 h1 = frag[(MH) * 512 + 256 + nt * 32];                       \
            uint4 l0 = frag[((MH)+1) * 512 +       nt * 32];                   \
            uint4 l1 = frag[((MH)+1) * 512 + 256 + nt * 32];                   \
            MMA_ONE(d[nt], ah[0], h0.x, h0.y);                                 \
            MMA(d[nt], ah[0], l0.x, l0.y);                                     \
            MMA(d[nt], ah[1], h0.z, h0.w);                                     \
            MMA(d[nt], ah[1], l0.z, l0.w);                                     \
            MMA(d[nt], ah[2], h1.x, h1.y);                                     \
            MMA(d[nt], ah[2], l1.x, l1.y);                                     \
            MMA(d[nt], ah[3], h1.z, h1.w);                                     \
            MMA(d[nt], ah[3], l1.z, l1.w);                                     \
        }                                                                      \
    } while (0)

    // precise nonlinearities (fp32 rcp)
#define BF_NONLIN()                                                            \
    do {                                                                       \
        _Pragma("unroll")                                                      \
        for (int nt = 0; nt < 8; nt++) {                                       \
            d[nt][0] = rcpa(d[nt][0]);                                         \
            d[nt][1] = rcpa(d[nt][1]);                                         \
            d[nt][2] = rcpa(d[nt][2]);                                         \
            d[nt][3] = rcpa(d[nt][3]);                                         \
        }                                                                      \
    } while (0)

#define AF_NONLIN()                                                            \
    do {                                                                       \
        _Pragma("unroll")                                                      \
        for (int nt = 0; nt < 8; nt++) {                                       \
            int cb = 8 * nt + 2 * t;                                           \
            float2 plo = *reinterpret_cast<const float2*>(ats + rlo + cb);     \
            float2 phi = *reinterpret_cast<const float2*>(ats + rhi + cb);     \
            d[nt][0] = plo.x * rcpa(d[nt][0]);                                 \
            d[nt][1] = plo.y * rcpa(d[nt][1]);                                 \
            d[nt][2] = phi.x * rcpa(d[nt][2]);                                 \
            d[nt][3] = phi.y * rcpa(d[nt][3]);                                 \
        }                                                                      \
    } while (0)

#define REPACK_FULL()                                                          \
    do {                                                                       \
        _Pragma("unroll")                                                      \
        for (int kt = 0; kt < 4; kt++) {                                       \
            split2h(d[2*kt][0],   d[2*kt][1],   ah[kt][0], al[kt][0]);         \
            split2h(d[2*kt][2],   d[2*kt][3],   ah[kt][1], al[kt][1]);         \
            split2h(d[2*kt+1][0], d[2*kt+1][1], ah[kt][2], al[kt][2]);         \
            split2h(d[2*kt+1][2], d[2*kt+1][3], ah[kt][3], al[kt][3]);         \
        }                                                                      \
    } while (0)

    // ---- phase 1: 14 cheap iterations ---------------------------------------
    #pragma unroll 1
    for (int it = 0; it < CHEAP_ITERS; ++it) {
        MMA_PHASE_CHEAP(0);        // BF-step: d = KT^T(AF) + 1
        BF_NONLIN_REPACK_CHEAP();  // A <- rcp(d) as fp16 pairs
        MMA_PHASE_CHEAP(2);        // AF-step: d = K'(BF') + 1
        AF_NONLIN_REPACK_CHEAP();  // A <- AT * rcp(d)
    }

    // ---- phase 2: precise BF (2-term, al==0) + precise AF, then final BF ----
    MMA_PHASE_FULL_NOAL(0);       // precise BF (ah pure fp16, al = 0 exactly)
    BF_NONLIN();
    REPACK_FULL();                // al first written here
    MMA_PHASE_FULL(2, MMA_ONE);   // precise AF (3-term)
    AF_NONLIN();
    REPACK_FULL();

    // final BF step: keep fp32 BF' for the output contraction
    MMA_PHASE_FULL(0, MMA_ONE);
    BF_NONLIN();

    // stash final BF' (fp32) into the AT region (AT dead; same-lane rw)
    #pragma unroll
    for (int nt = 0; nt < 8; nt++) {
        int cb = 8 * nt + 2 * t;
        *reinterpret_cast<float2*>(ats + rlo + cb) =
            make_float2(d[nt][0], d[nt][1]);
        *reinterpret_cast<float2*>(ats + rhi + cb) =
            make_float2(d[nt][2], d[nt][3]);
    }

    // epilogue: H = AF @ M' (C = 0); y = sum_j BF'_j H_j
    MMA_PHASE_FULL(4, MMA_Z);

    float y0 = 0.f, y1 = 0.f;
    #pragma unroll
    for (int nt = 0; nt < 8; nt++) {
        int cb = 8 * nt + 2 * t;
        float2 blo = *reinterpret_cast<const float2*>(ats + rlo + cb);
        float2 bhi = *reinterpret_cast<const float2*>(ats + rhi + cb);
        y0 = fmaf(blo.x, d[nt][0], fmaf(blo.y, d[nt][1], y0));
        y1 = fmaf(bhi.x, d[nt][2], fmaf(bhi.y, d[nt][3], y1));
    }

    y0 += __shfl_xor_sync(0xFFFFFFFFu, y0, 1);
    y0 += __shfl_xor_sync(0xFFFFFFFFu, y0, 2);
    y1 += __shfl_xor_sync(0xFFFFFFFFu, y1, 1);
    y1 += __shfl_xor_sync(0xFFFFFFFFu, y1, 2);

    if (t == 0) {
        float bc = fminf(fmaxf(braw[0], -10.0f), 10.0f);
        size_t base = (size_t)bid * ROWS_PER_CTA + rb + g;
        out[base + 0] = y0 + bc;
        out[base + 8] = y1 + bc;
    }
}

extern "C" void kernel_launch(void* const* d_in, const int* in_sizes, int n_in,
                              void* d_out, int out_size)
{
    const float* AT    = (const float*)d_in[0];
    const float* Kraw  = (const float*)d_in[1];
    const float* BTraw = (const float*)d_in[2];
    const float* Wraw  = (const float*)d_in[3];
    const float* braw  = (const float*)d_in[4];
    float* out = (float*)d_out;

    const int B = in_sizes[0] / N_DIM;          // 16384
    const int grid = B / ROWS_PER_CTA;          // 128

    cudaFuncSetAttribute(cnet_mma_kernel,
                         cudaFuncAttributeMaxDynamicSharedMemorySize,
                         SMEM_TOTAL);

    cnet_mma_kernel<<<grid, THREADS, SMEM_TOTAL>>>(
        AT, Kraw, BTraw, Wraw, braw, out);
}